// round 8
// baseline (speedup 1.0000x reference)
#include <cuda_runtime.h>
#include <cuda_bf16.h>
#include <math.h>
#include <stdint.h>

#define N_NODES 50000
#define N_EDGES 800000
#define HID     96
#define BM      128
#define KST     104        // bf16 elems per row; 208B stride -> LDSM conflict-free

// smem byte offsets
#define SM_AHI  0
#define SM_ALO  26624      // 128*104*2
#define SM_BHI  53248
#define SM_BLO  73216      // SM_BHI + 96*104*2
#define SM_BIAS 93184
#define SM_TOT  93568

#define WTILE_BYTES 19968            // 96*104*2
#define WMAT_BYTES  (2 * WTILE_BYTES)

// Scratch (device globals; no allocation allowed)
__device__ float g_h[N_NODES * HID];
__device__ float g_aggr[N_NODES * HID];
__device__ float g_x[N_NODES * HID];
__device__ float g_t[N_NODES * HID];
__device__ unsigned char g_wcvt[3 * WMAT_BYTES];  // per matrix: hi tile | lo tile, [n][KST]

__device__ __forceinline__ float gelu_exact(float x) {
    return 0.5f * x * (1.0f + erff(x * 0.7071067811865476f));
}
__device__ __forceinline__ void bf16_split(float v, uint16_t& hi, uint16_t& lo) {
    __nv_bfloat16 h = __float2bfloat16(v);
    __nv_bfloat16 l = __float2bfloat16(v - __bfloat162float(h));
    hi = __bfloat16_as_ushort(h);
    lo = __bfloat16_as_ushort(l);
}
__device__ __forceinline__ uint32_t pack_bf16x2(float a_upper, float b_lower) {
    uint32_t d;
    asm("cvt.rn.bf16x2.f32 %0, %1, %2;" : "=r"(d) : "f"(a_upper), "f"(b_lower));
    return d;
}
__device__ __forceinline__ uint32_t smem_u32(const void* p) {
    uint32_t a;
    asm("{ .reg .u64 t; cvta.to.shared.u64 t, %1; cvt.u32.u64 %0, t; }" : "=r"(a) : "l"(p));
    return a;
}
__device__ __forceinline__ void ldsm4(uint32_t& r0, uint32_t& r1, uint32_t& r2, uint32_t& r3,
                                      uint32_t addr) {
    asm volatile("ldmatrix.sync.aligned.m8n8.x4.shared.b16 {%0,%1,%2,%3}, [%4];"
                 : "=r"(r0), "=r"(r1), "=r"(r2), "=r"(r3) : "r"(addr));
}

// One-time W convert, parallel: 96 blocks, block b handles slice (b%32) of matrix (b/32).
__global__ void wconv_kernel(const float* __restrict__ W0, const float* __restrict__ W1,
                             const float* __restrict__ W2) {
    const int m = blockIdx.x >> 5, s = blockIdx.x & 31;
    const float* W = (m == 0) ? W0 : (m == 1) ? W1 : W2;
    uint16_t* dhi = (uint16_t*)(g_wcvt + m * WMAT_BYTES);
    uint16_t* dlo = (uint16_t*)(g_wcvt + m * WMAT_BYTES + WTILE_BYTES);
    const int e0 = s * 288, e1 = e0 + 288;     // 9216/32
    for (int e = e0 + threadIdx.x; e < e1; e += blockDim.x) {
        int k = e / HID, n = e - (e / HID) * HID;
        uint16_t hi, lo;
        bf16_split(W[e], hi, lo);
        dhi[n * KST + k] = hi;
        dlo[n * KST + k] = lo;
    }
}

// MODE 0 (PRE):  A = x_feat;          out = g_h = gelu(A@W+b); also zero g_aggr rows
// MODE 1 (MID):  A = x_feat + g_aggr; out = g_t = gelu(A@W+b); also persist A into g_x
// MODE 2 (POST): A = g_t;             out = g_x + gelu(A@W+b)  (final output)
template <int MODE>
__global__ __launch_bounds__(256, 2)
void gemm_kernel(const float* __restrict__ A0,
                 const unsigned char* __restrict__ wcvt,
                 const float* __restrict__ bias,
                 float* __restrict__ out) {
    extern __shared__ char smem[];
    uint16_t* Ahi = (uint16_t*)(smem + SM_AHI);
    uint16_t* Alo = (uint16_t*)(smem + SM_ALO);
    float*    Bsm = (float*)(smem + SM_BIAS);

    const int tid  = threadIdx.x;
    const int row0 = blockIdx.x * BM;

    // ---- W tiles: layout-preserving vector copy (hi|lo contiguous, 2496 float4) ----
    {
        const float4* src = (const float4*)wcvt;
        float4* dst = (float4*)(smem + SM_BHI);
#pragma unroll
        for (int i = 0; i < 10; i++) {
            int idx = tid + 256 * i;
            if (idx < WMAT_BYTES / 16) dst[idx] = src[idx];
        }
    }
    if (tid < 24) ((float4*)Bsm)[tid] = ((const float4*)bias)[tid];

    // ---- X tile: load fp32, MODE transform, packed bf16 split, store ----
#pragma unroll
    for (int i = 0; i < 12; i++) {
        int idx4 = tid + 256 * i;
        int r = idx4 / 24, c4 = idx4 - (idx4 / 24) * 24;
        int row = row0 + r;
        float4 v = make_float4(0.f, 0.f, 0.f, 0.f);
        if (row < N_NODES) {
            v = ((const float4*)(A0 + (size_t)row * HID))[c4];
            if (MODE == 1) {
                float4 a = ((const float4*)(g_aggr + (size_t)row * HID))[c4];
                v.x += a.x; v.y += a.y; v.z += a.z; v.w += a.w;
                ((float4*)(g_x + (size_t)row * HID))[c4] = v;   // persist residual-1
            }
            if (MODE == 0)
                ((float4*)(g_aggr + (size_t)row * HID))[c4] = make_float4(0.f, 0.f, 0.f, 0.f);
        }
        uint32_t h01 = pack_bf16x2(v.y, v.x);
        uint32_t h23 = pack_bf16x2(v.w, v.z);
        float hx = __uint_as_float(h01 << 16);
        float hy = __uint_as_float(h01 & 0xffff0000u);
        float hz = __uint_as_float(h23 << 16);
        float hw = __uint_as_float(h23 & 0xffff0000u);
        uint32_t l01 = pack_bf16x2(v.y - hy, v.x - hx);
        uint32_t l23 = pack_bf16x2(v.w - hw, v.z - hz);
        int eo = r * KST + c4 * 4;
        *(uint2*)(Ahi + eo) = make_uint2(h01, h23);
        *(uint2*)(Alo + eo) = make_uint2(l01, l23);
    }
    __syncthreads();

    // ---- MMA: warp w covers rows m0..m0+31, cols n0..n0+47 ----
    const int w  = tid >> 5;
    const int l  = tid & 31;
    const int m0 = (w & 3) * 32;
    const int n0 = (w >> 2) * 48;

    const uint32_t sbase = smem_u32(smem);
    uint32_t aoff[2], boff[3];
#pragma unroll
    for (int mt = 0; mt < 2; mt++)
        aoff[mt] = (uint32_t)((m0 + mt * 16 + (l & 15)) * KST + (l >> 4) * 8);
#pragma unroll
    for (int p = 0; p < 3; p++)
        boff[p] = (uint32_t)((n0 + p * 16 + (l >> 4) * 8 + (l & 7)) * KST + ((l >> 3) & 1) * 8);

    float acc[2][6][4];
#pragma unroll
    for (int mt = 0; mt < 2; mt++)
#pragma unroll
        for (int nt = 0; nt < 6; nt++)
#pragma unroll
            for (int q = 0; q < 4; q++) acc[mt][nt][q] = 0.f;

#pragma unroll
    for (int term = 0; term < 3; term++) {
        const uint32_t abase = sbase + ((term == 1) ? SM_ALO : SM_AHI);
        const uint32_t bbase = sbase + ((term == 2) ? SM_BLO : SM_BHI);
#pragma unroll
        for (int ks = 0; ks < 6; ks++) {
            const uint32_t k0 = ks * 16;
            uint32_t af[2][4];
#pragma unroll
            for (int mt = 0; mt < 2; mt++)
                ldsm4(af[mt][0], af[mt][1], af[mt][2], af[mt][3],
                      abase + 2 * (aoff[mt] + k0));
            uint32_t bf[6][2];
#pragma unroll
            for (int p = 0; p < 3; p++)
                ldsm4(bf[2 * p][0], bf[2 * p][1], bf[2 * p + 1][0], bf[2 * p + 1][1],
                      bbase + 2 * (boff[p] + k0));
#pragma unroll
            for (int mt = 0; mt < 2; mt++)
#pragma unroll
                for (int nt = 0; nt < 6; nt++)
                    asm volatile(
                        "mma.sync.aligned.m16n8k16.row.col.f32.bf16.bf16.f32 "
                        "{%0,%1,%2,%3}, {%4,%5,%6,%7}, {%8,%9}, {%0,%1,%2,%3};"
                        : "+f"(acc[mt][nt][0]), "+f"(acc[mt][nt][1]),
                          "+f"(acc[mt][nt][2]), "+f"(acc[mt][nt][3])
                        : "r"(af[mt][0]), "r"(af[mt][1]), "r"(af[mt][2]), "r"(af[mt][3]),
                          "r"(bf[nt][0]), "r"(bf[nt][1]));
        }
    }

    // ---- epilogue straight from registers ----
    const int lr = l >> 2;
    const int lk = 2 * (l & 3);
#pragma unroll
    for (int mt = 0; mt < 2; mt++) {
#pragma unroll
        for (int nt = 0; nt < 6; nt++) {
            int col = n0 + nt * 8 + lk;
            float bx = Bsm[col], by = Bsm[col + 1];
            int r1 = row0 + m0 + mt * 16 + lr;
            int r2 = r1 + 8;
            if (r1 < N_NODES) {
                float gx = gelu_exact(acc[mt][nt][0] + bx);
                float gy = gelu_exact(acc[mt][nt][1] + by);
                size_t o = (size_t)r1 * HID + col;
                if (MODE == 2) {
                    float2 xv = *(const float2*)(g_x + o);
                    gx += xv.x; gy += xv.y;
                }
                *(float2*)(out + o) = make_float2(gx, gy);
            }
            if (r2 < N_NODES) {
                float gx = gelu_exact(acc[mt][nt][2] + bx);
                float gy = gelu_exact(acc[mt][nt][3] + by);
                size_t o = (size_t)r2 * HID + col;
                if (MODE == 2) {
                    float2 xv = *(const float2*)(g_x + o);
                    gx += xv.x; gy += xv.y;
                }
                *(float2*)(out + o) = make_float2(gx, gy);
            }
        }
    }
}

// Edge scatter: one thread per quarter-row (4 float4s). Index loads amortized 4x.
__global__ __launch_bounds__(256)
void edge_kernel(const float* __restrict__ bases,
                 const int* __restrict__ src,
                 const int* __restrict__ dst) {
    int idx = blockIdx.x * 256 + threadIdx.x;           // < 4.8M
    if (idx >= N_EDGES * 6) return;
    int e = idx / 6;
    int q = idx - e * 6;
    int s = __ldg(src + e);
    int d = __ldg(dst + e);
    const float4* b4 = (const float4*)bases + (size_t)e * 24 + q * 4;
    const float4* h4 = (const float4*)(g_h + (size_t)s * HID) + q * 4;
    float* p = g_aggr + (size_t)d * HID + q * 16;
#pragma unroll
    for (int j = 0; j < 4; j++) {
        float4 b = b4[j];
        float4 h = h4[j];
        float4 m = make_float4(b.x * h.x, b.y * h.y, b.z * h.z, b.w * h.w);
        asm volatile("red.global.add.v4.f32 [%0], {%1, %2, %3, %4};"
                     :: "l"(p + j * 4), "f"(m.x), "f"(m.y), "f"(m.z), "f"(m.w)
                     : "memory");
    }
}

extern "C" void kernel_launch(void* const* d_in, const int* in_sizes, int n_in,
                              void* d_out, int out_size) {
    const float* x_feat = (const float*)d_in[0];
    const float* bases  = (const float*)d_in[1];
    const float* W_pre  = (const float*)d_in[2];
    const float* b_pre  = (const float*)d_in[3];
    const float* W1     = (const float*)d_in[4];
    const float* b1     = (const float*)d_in[5];
    const float* W2     = (const float*)d_in[6];
    const float* b2     = (const float*)d_in[7];
    const int*   src    = (const int*)d_in[8];
    const int*   dst    = (const int*)d_in[9];
    float* out = (float*)d_out;

    cudaFuncSetAttribute(gemm_kernel<0>, cudaFuncAttributeMaxDynamicSharedMemorySize, SM_TOT);
    cudaFuncSetAttribute(gemm_kernel<1>, cudaFuncAttributeMaxDynamicSharedMemorySize, SM_TOT);
    cudaFuncSetAttribute(gemm_kernel<2>, cudaFuncAttributeMaxDynamicSharedMemorySize, SM_TOT);

    float* g_h_p;  cudaGetSymbolAddress((void**)&g_h_p, g_h);
    float* g_t_p;  cudaGetSymbolAddress((void**)&g_t_p, g_t);
    unsigned char* wcvt_p; cudaGetSymbolAddress((void**)&wcvt_p, g_wcvt);

    const int gemm_grid = (N_NODES + BM - 1) / BM;   // 391
    const int edge_grid = (N_EDGES * 6 + 255) / 256;

    wconv_kernel<<<96, 256>>>(W_pre, W1, W2);
    // 1) h = gelu(x_feat @ W_pre + b_pre); zero aggr
    gemm_kernel<0><<<gemm_grid, 256, SM_TOT>>>(x_feat, wcvt_p, b_pre, g_h_p);
    // 2) aggr[dst] += h[src] * bases
    edge_kernel<<<edge_grid, 256>>>(bases, src, dst);
    // 3) x = x_feat + aggr (persisted); t = gelu(x @ W1 + b1)
    gemm_kernel<1><<<gemm_grid, 256, SM_TOT>>>(x_feat, wcvt_p + WMAT_BYTES, b1, g_t_p);
    // 4) out = x + gelu(t @ W2 + b2)
    gemm_kernel<2><<<gemm_grid, 256, SM_TOT>>>(g_t_p, wcvt_p + 2 * WMAT_BYTES, b2, out);
}

// round 9
// speedup vs baseline: 1.3414x; 1.3414x over previous
#include <cuda_runtime.h>
#include <cuda_bf16.h>
#include <math.h>
#include <stdint.h>

#define N_NODES 50000
#define N_EDGES 800000
#define HID     96
#define BM      128
#define KST     104        // bf16 elems per row; 208B stride -> LDSM conflict-free

// smem byte offsets
#define SM_AHI  0
#define SM_ALO  26624      // 128*104*2
#define SM_BHI  53248
#define SM_BLO  73216      // SM_BHI + 96*104*2
#define SM_BIAS 93184
#define SM_TOT  93568

#define WTILE_BYTES 19968            // 96*104*2
#define WMAT_BYTES  (2 * WTILE_BYTES)

// Scratch (device globals; no allocation allowed)
__device__ float g_h[N_NODES * HID];
__device__ float g_aggr[N_NODES * HID];
__device__ float g_x[N_NODES * HID];
__device__ float g_t[N_NODES * HID];
__device__ unsigned char g_wcvt[3 * WMAT_BYTES];  // per matrix: hi tile | lo tile, [n][KST]

__device__ __forceinline__ float gelu_exact(float x) {
    return 0.5f * x * (1.0f + erff(x * 0.7071067811865476f));
}
__device__ __forceinline__ void bf16_split(float v, uint16_t& hi, uint16_t& lo) {
    __nv_bfloat16 h = __float2bfloat16(v);
    __nv_bfloat16 l = __float2bfloat16(v - __bfloat162float(h));
    hi = __bfloat16_as_ushort(h);
    lo = __bfloat16_as_ushort(l);
}
__device__ __forceinline__ uint32_t pack_bf16x2(float a_upper, float b_lower) {
    uint32_t d;
    asm("cvt.rn.bf16x2.f32 %0, %1, %2;" : "=r"(d) : "f"(a_upper), "f"(b_lower));
    return d;
}
__device__ __forceinline__ uint32_t smem_u32(const void* p) {
    uint32_t a;
    asm("{ .reg .u64 t; cvta.to.shared.u64 t, %1; cvt.u32.u64 %0, t; }" : "=r"(a) : "l"(p));
    return a;
}
__device__ __forceinline__ void ldsm4(uint32_t& r0, uint32_t& r1, uint32_t& r2, uint32_t& r3,
                                      uint32_t addr) {
    asm volatile("ldmatrix.sync.aligned.m8n8.x4.shared.b16 {%0,%1,%2,%3}, [%4];"
                 : "=r"(r0), "=r"(r1), "=r"(r2), "=r"(r3) : "r"(addr));
}
#define MMA_BF16(acc, a0, a1, a2, a3, b0, b1)                                    \
    asm volatile(                                                                \
        "mma.sync.aligned.m16n8k16.row.col.f32.bf16.bf16.f32 "                   \
        "{%0,%1,%2,%3}, {%4,%5,%6,%7}, {%8,%9}, {%0,%1,%2,%3};"                  \
        : "+f"((acc)[0]), "+f"((acc)[1]), "+f"((acc)[2]), "+f"((acc)[3])         \
        : "r"(a0), "r"(a1), "r"(a2), "r"(a3), "r"(b0), "r"(b1))

// One-time W convert, parallel: 96 blocks, block b handles slice (b%32) of matrix (b/32).
__global__ void wconv_kernel(const float* __restrict__ W0, const float* __restrict__ W1,
                             const float* __restrict__ W2) {
    const int m = blockIdx.x >> 5, s = blockIdx.x & 31;
    const float* W = (m == 0) ? W0 : (m == 1) ? W1 : W2;
    uint16_t* dhi = (uint16_t*)(g_wcvt + m * WMAT_BYTES);
    uint16_t* dlo = (uint16_t*)(g_wcvt + m * WMAT_BYTES + WTILE_BYTES);
    const int e0 = s * 288, e1 = e0 + 288;     // 9216/32
    for (int e = e0 + threadIdx.x; e < e1; e += blockDim.x) {
        int k = e / HID, n = e - (e / HID) * HID;
        uint16_t hi, lo;
        bf16_split(W[e], hi, lo);
        dhi[n * KST + k] = hi;
        dlo[n * KST + k] = lo;
    }
}

// MODE 0 (PRE):  A = x_feat;          out = g_h = gelu(A@W+b); also zero g_aggr rows
// MODE 1 (MID):  A = x_feat + g_aggr; out = g_t = gelu(A@W+b); also persist A into g_x
// MODE 2 (POST): A = g_t;             out = g_x + gelu(A@W+b)  (final output)
template <int MODE>
__global__ __launch_bounds__(256, 2)
void gemm_kernel(const float* __restrict__ A0,
                 const unsigned char* __restrict__ wcvt,
                 const float* __restrict__ bias,
                 float* __restrict__ out) {
    extern __shared__ char smem[];
    uint16_t* Ahi = (uint16_t*)(smem + SM_AHI);
    uint16_t* Alo = (uint16_t*)(smem + SM_ALO);
    float*    Bsm = (float*)(smem + SM_BIAS);

    const int tid  = threadIdx.x;
    const int row0 = blockIdx.x * BM;

    // ---- W tiles: layout-preserving vector copy (hi|lo contiguous, 2496 float4) ----
    {
        const float4* src = (const float4*)wcvt;
        float4* dst = (float4*)(smem + SM_BHI);
#pragma unroll
        for (int i = 0; i < 10; i++) {
            int idx = tid + 256 * i;
            if (idx < WMAT_BYTES / 16) dst[idx] = src[idx];
        }
    }
    if (tid < 24) ((float4*)Bsm)[tid] = ((const float4*)bias)[tid];

    // ---- X tile: load fp32, MODE transform, packed bf16 split, store ----
#pragma unroll
    for (int i = 0; i < 12; i++) {
        int idx4 = tid + 256 * i;
        int r = idx4 / 24, c4 = idx4 - (idx4 / 24) * 24;
        int row = row0 + r;
        float4 v = make_float4(0.f, 0.f, 0.f, 0.f);
        if (row < N_NODES) {
            v = ((const float4*)(A0 + (size_t)row * HID))[c4];
            if (MODE == 1) {
                float4 a = ((const float4*)(g_aggr + (size_t)row * HID))[c4];
                v.x += a.x; v.y += a.y; v.z += a.z; v.w += a.w;
                ((float4*)(g_x + (size_t)row * HID))[c4] = v;   // persist residual-1
            }
            if (MODE == 0)
                ((float4*)(g_aggr + (size_t)row * HID))[c4] = make_float4(0.f, 0.f, 0.f, 0.f);
        }
        uint32_t h01 = pack_bf16x2(v.y, v.x);
        uint32_t h23 = pack_bf16x2(v.w, v.z);
        float hx = __uint_as_float(h01 << 16);
        float hy = __uint_as_float(h01 & 0xffff0000u);
        float hz = __uint_as_float(h23 << 16);
        float hw = __uint_as_float(h23 & 0xffff0000u);
        uint32_t l01 = pack_bf16x2(v.y - hy, v.x - hx);
        uint32_t l23 = pack_bf16x2(v.w - hw, v.z - hz);
        int eo = r * KST + c4 * 4;
        *(uint2*)(Ahi + eo) = make_uint2(h01, h23);
        *(uint2*)(Alo + eo) = make_uint2(l01, l23);
    }
    __syncthreads();

    // ---- MMA: warp w covers rows m0..m0+31, cols n0..n0+47; ks-outer fused terms ----
    const int w  = tid >> 5;
    const int l  = tid & 31;
    const int m0 = (w & 3) * 32;
    const int n0 = (w >> 2) * 48;

    const uint32_t sbase = smem_u32(smem);
    uint32_t aoff[2], boff[3];
#pragma unroll
    for (int mt = 0; mt < 2; mt++)
        aoff[mt] = (uint32_t)((m0 + mt * 16 + (l & 15)) * KST + (l >> 4) * 8);
#pragma unroll
    for (int p = 0; p < 3; p++)
        boff[p] = (uint32_t)((n0 + p * 16 + (l >> 4) * 8 + (l & 7)) * KST + ((l >> 3) & 1) * 8);

    float acc[2][6][4];
#pragma unroll
    for (int mt = 0; mt < 2; mt++)
#pragma unroll
        for (int nt = 0; nt < 6; nt++)
#pragma unroll
            for (int q = 0; q < 4; q++) acc[mt][nt][q] = 0.f;

#pragma unroll
    for (int ks = 0; ks < 6; ks++) {
        const uint32_t k0 = ks * 16;
        uint32_t aH[2][4], aL[2][4], bH[6][2], bL[6][2];
#pragma unroll
        for (int mt = 0; mt < 2; mt++) {
            ldsm4(aH[mt][0], aH[mt][1], aH[mt][2], aH[mt][3],
                  sbase + SM_AHI + 2 * (aoff[mt] + k0));
            ldsm4(aL[mt][0], aL[mt][1], aL[mt][2], aL[mt][3],
                  sbase + SM_ALO + 2 * (aoff[mt] + k0));
        }
#pragma unroll
        for (int p = 0; p < 3; p++) {
            ldsm4(bH[2 * p][0], bH[2 * p][1], bH[2 * p + 1][0], bH[2 * p + 1][1],
                  sbase + SM_BHI + 2 * (boff[p] + k0));
            ldsm4(bL[2 * p][0], bL[2 * p][1], bL[2 * p + 1][0], bL[2 * p + 1][1],
                  sbase + SM_BLO + 2 * (boff[p] + k0));
        }
        // term hi*hi
#pragma unroll
        for (int mt = 0; mt < 2; mt++)
#pragma unroll
            for (int nt = 0; nt < 6; nt++)
                MMA_BF16(acc[mt][nt], aH[mt][0], aH[mt][1], aH[mt][2], aH[mt][3],
                         bH[nt][0], bH[nt][1]);
        // term hi*lo
#pragma unroll
        for (int mt = 0; mt < 2; mt++)
#pragma unroll
            for (int nt = 0; nt < 6; nt++)
                MMA_BF16(acc[mt][nt], aH[mt][0], aH[mt][1], aH[mt][2], aH[mt][3],
                         bL[nt][0], bL[nt][1]);
        // term lo*hi
#pragma unroll
        for (int mt = 0; mt < 2; mt++)
#pragma unroll
            for (int nt = 0; nt < 6; nt++)
                MMA_BF16(acc[mt][nt], aL[mt][0], aL[mt][1], aL[mt][2], aL[mt][3],
                         bH[nt][0], bH[nt][1]);
    }

    // ---- epilogue straight from registers ----
    const int lr = l >> 2;
    const int lk = 2 * (l & 3);
#pragma unroll
    for (int mt = 0; mt < 2; mt++) {
#pragma unroll
        for (int nt = 0; nt < 6; nt++) {
            int col = n0 + nt * 8 + lk;
            float bx = Bsm[col], by = Bsm[col + 1];
            int r1 = row0 + m0 + mt * 16 + lr;
            int r2 = r1 + 8;
            if (r1 < N_NODES) {
                float gx = gelu_exact(acc[mt][nt][0] + bx);
                float gy = gelu_exact(acc[mt][nt][1] + by);
                size_t o = (size_t)r1 * HID + col;
                if (MODE == 2) {
                    float2 xv = *(const float2*)(g_x + o);
                    gx += xv.x; gy += xv.y;
                }
                *(float2*)(out + o) = make_float2(gx, gy);
            }
            if (r2 < N_NODES) {
                float gx = gelu_exact(acc[mt][nt][2] + bx);
                float gy = gelu_exact(acc[mt][nt][3] + by);
                size_t o = (size_t)r2 * HID + col;
                if (MODE == 2) {
                    float2 xv = *(const float2*)(g_x + o);
                    gx += xv.x; gy += xv.y;
                }
                *(float2*)(out + o) = make_float2(gx, gy);
            }
        }
    }
}

// Edge scatter: aggr[dst] += h[src] * bases, one float4 per thread (fully coalesced).
__global__ __launch_bounds__(256)
void edge_kernel(const float* __restrict__ bases,
                 const int* __restrict__ src,
                 const int* __restrict__ dst) {
    int idx = blockIdx.x * 256 + threadIdx.x;
    if (idx >= N_EDGES * 24) return;
    int e = idx / 24;
    int c = idx - e * 24;
    int s = src[e];
    int d = dst[e];
    float4 b  = ((const float4*)bases)[idx];
    float4 hv = ((const float4*)(g_h + (size_t)s * HID))[c];
    float4 m  = make_float4(b.x * hv.x, b.y * hv.y, b.z * hv.z, b.w * hv.w);
    float* p = g_aggr + (size_t)d * HID + c * 4;
    asm volatile("red.global.add.v4.f32 [%0], {%1, %2, %3, %4};"
                 :: "l"(p), "f"(m.x), "f"(m.y), "f"(m.z), "f"(m.w)
                 : "memory");
}

extern "C" void kernel_launch(void* const* d_in, const int* in_sizes, int n_in,
                              void* d_out, int out_size) {
    const float* x_feat = (const float*)d_in[0];
    const float* bases  = (const float*)d_in[1];
    const float* W_pre  = (const float*)d_in[2];
    const float* b_pre  = (const float*)d_in[3];
    const float* W1     = (const float*)d_in[4];
    const float* b1     = (const float*)d_in[5];
    const float* W2     = (const float*)d_in[6];
    const float* b2     = (const float*)d_in[7];
    const int*   src    = (const int*)d_in[8];
    const int*   dst    = (const int*)d_in[9];
    float* out = (float*)d_out;

    cudaFuncSetAttribute(gemm_kernel<0>, cudaFuncAttributeMaxDynamicSharedMemorySize, SM_TOT);
    cudaFuncSetAttribute(gemm_kernel<1>, cudaFuncAttributeMaxDynamicSharedMemorySize, SM_TOT);
    cudaFuncSetAttribute(gemm_kernel<2>, cudaFuncAttributeMaxDynamicSharedMemorySize, SM_TOT);

    float* g_h_p;  cudaGetSymbolAddress((void**)&g_h_p, g_h);
    float* g_t_p;  cudaGetSymbolAddress((void**)&g_t_p, g_t);
    unsigned char* wcvt_p; cudaGetSymbolAddress((void**)&wcvt_p, g_wcvt);

    const int gemm_grid = (N_NODES + BM - 1) / BM;   // 391
    const int edge_grid = (N_EDGES * 24 + 255) / 256;

    wconv_kernel<<<96, 256>>>(W_pre, W1, W2);
    // 1) h = gelu(x_feat @ W_pre + b_pre); zero aggr
    gemm_kernel<0><<<gemm_grid, 256, SM_TOT>>>(x_feat, wcvt_p, b_pre, g_h_p);
    // 2) aggr[dst] += h[src] * bases
    edge_kernel<<<edge_grid, 256>>>(bases, src, dst);
    // 3) x = x_feat + aggr (persisted); t = gelu(x @ W1 + b1)
    gemm_kernel<1><<<gemm_grid, 256, SM_TOT>>>(x_feat, wcvt_p + WMAT_BYTES, b1, g_t_p);
    // 4) out = x + gelu(t @ W2 + b2)
    gemm_kernel<2><<<gemm_grid, 256, SM_TOT>>>(g_t_p, wcvt_p + 2 * WMAT_BYTES, b2, out);
}

// round 10
// speedup vs baseline: 1.4303x; 1.0662x over previous
#include <cuda_runtime.h>
#include <cuda_bf16.h>
#include <math.h>
#include <stdint.h>

#define N_NODES 50000
#define N_EDGES 800000
#define HID     96
#define BM      128
#define KST     104        // bf16 elems per row; 208B stride -> LDSM conflict-free

// smem byte offsets
#define SM_AHI  0
#define SM_ALO  26624      // 128*104*2
#define SM_BHI  53248
#define SM_BLO  73216      // SM_BHI + 96*104*2
#define SM_BIAS 93184
#define SM_TOT  93568

#define WTILE_BYTES 19968            // 96*104*2
#define WMAT_BYTES  (2 * WTILE_BYTES)

// Scratch (device globals; no allocation allowed)
__device__ float g_h[N_NODES * HID];
__device__ float g_aggr[N_NODES * HID];   // gemm<0> seeds with x_feat; edge adds msgs -> becomes x
__device__ float g_t[N_NODES * HID];
__device__ unsigned char g_wcvt[3 * WMAT_BYTES];  // per matrix: hi tile | lo tile, [n][KST]

__device__ __forceinline__ float gelu_exact(float x) {
    return 0.5f * x * (1.0f + erff(x * 0.7071067811865476f));
}
__device__ __forceinline__ void bf16_split(float v, uint16_t& hi, uint16_t& lo) {
    __nv_bfloat16 h = __float2bfloat16(v);
    __nv_bfloat16 l = __float2bfloat16(v - __bfloat162float(h));
    hi = __bfloat16_as_ushort(h);
    lo = __bfloat16_as_ushort(l);
}
__device__ __forceinline__ uint32_t pack_bf16x2(float a_upper, float b_lower) {
    uint32_t d;
    asm("cvt.rn.bf16x2.f32 %0, %1, %2;" : "=r"(d) : "f"(a_upper), "f"(b_lower));
    return d;
}
__device__ __forceinline__ uint32_t smem_u32(const void* p) {
    uint32_t a;
    asm("{ .reg .u64 t; cvta.to.shared.u64 t, %1; cvt.u32.u64 %0, t; }" : "=r"(a) : "l"(p));
    return a;
}
__device__ __forceinline__ void ldsm4(uint32_t& r0, uint32_t& r1, uint32_t& r2, uint32_t& r3,
                                      uint32_t addr) {
    asm volatile("ldmatrix.sync.aligned.m8n8.x4.shared.b16 {%0,%1,%2,%3}, [%4];"
                 : "=r"(r0), "=r"(r1), "=r"(r2), "=r"(r3) : "r"(addr));
}
#define MMA_BF16(acc, a0, a1, a2, a3, b0, b1)                                    \
    asm volatile(                                                                \
        "mma.sync.aligned.m16n8k16.row.col.f32.bf16.bf16.f32 "                   \
        "{%0,%1,%2,%3}, {%4,%5,%6,%7}, {%8,%9}, {%0,%1,%2,%3};"                  \
        : "+f"((acc)[0]), "+f"((acc)[1]), "+f"((acc)[2]), "+f"((acc)[3])         \
        : "r"(a0), "r"(a1), "r"(a2), "r"(a3), "r"(b0), "r"(b1))

// One-time W convert, parallel: 96 blocks, block b handles slice (b%32) of matrix (b/32).
__global__ void wconv_kernel(const float* __restrict__ W0, const float* __restrict__ W1,
                             const float* __restrict__ W2) {
    const int m = blockIdx.x >> 5, s = blockIdx.x & 31;
    const float* W = (m == 0) ? W0 : (m == 1) ? W1 : W2;
    uint16_t* dhi = (uint16_t*)(g_wcvt + m * WMAT_BYTES);
    uint16_t* dlo = (uint16_t*)(g_wcvt + m * WMAT_BYTES + WTILE_BYTES);
    const int e0 = s * 288, e1 = e0 + 288;     // 9216/32
    for (int e = e0 + threadIdx.x; e < e1; e += blockDim.x) {
        int k = e / HID, n = e - (e / HID) * HID;
        uint16_t hi, lo;
        bf16_split(W[e], hi, lo);
        dhi[n * KST + k] = hi;
        dlo[n * KST + k] = lo;
    }
}

// MODE 0 (PRE):  A = x_feat; out = g_h = gelu(A@W+b); seed g_aggr = x_feat
// MODE 1 (MID):  A = g_aggr (== x after edge); out = g_t = gelu(A@W+b)
// MODE 2 (POST): A = g_t;    out = g_aggr + gelu(A@W+b)  (final output)
template <int MODE>
__global__ __launch_bounds__(256, 2)
void gemm_kernel(const float* __restrict__ A0,
                 const unsigned char* __restrict__ wcvt,
                 const float* __restrict__ bias,
                 float* __restrict__ out) {
    extern __shared__ char smem[];
    uint16_t* Ahi = (uint16_t*)(smem + SM_AHI);
    uint16_t* Alo = (uint16_t*)(smem + SM_ALO);
    float*    Bsm = (float*)(smem + SM_BIAS);

    const int tid  = threadIdx.x;
    const int row0 = blockIdx.x * BM;
    const uint32_t sbase = smem_u32(smem);

    // ---- W tiles: async layout-preserving copy (hi|lo contiguous, 2496 x 16B) ----
    {
        const char* src = (const char*)wcvt;
#pragma unroll
        for (int i = 0; i < 10; i++) {
            int idx = tid + 256 * i;
            if (idx < WMAT_BYTES / 16) {
                uint32_t d = sbase + SM_BHI + 16 * idx;
                asm volatile("cp.async.cg.shared.global [%0], [%1], 16;"
                             :: "r"(d), "l"(src + 16 * idx) : "memory");
            }
        }
        asm volatile("cp.async.commit_group;" ::: "memory");
    }
    if (tid < 24) ((float4*)Bsm)[tid] = ((const float4*)bias)[tid];

    // ---- X tile: load fp32, packed bf16 split, store; MODE 0 seeds g_aggr ----
#pragma unroll
    for (int i = 0; i < 12; i++) {
        int idx4 = tid + 256 * i;
        int r = idx4 / 24, c4 = idx4 - (idx4 / 24) * 24;
        int row = row0 + r;
        float4 v = make_float4(0.f, 0.f, 0.f, 0.f);
        if (row < N_NODES) {
            v = ((const float4*)(A0 + (size_t)row * HID))[c4];
            if (MODE == 0)
                ((float4*)(g_aggr + (size_t)row * HID))[c4] = v;   // seed aggr with x_feat
        }
        uint32_t h01 = pack_bf16x2(v.y, v.x);
        uint32_t h23 = pack_bf16x2(v.w, v.z);
        float hx = __uint_as_float(h01 << 16);
        float hy = __uint_as_float(h01 & 0xffff0000u);
        float hz = __uint_as_float(h23 << 16);
        float hw = __uint_as_float(h23 & 0xffff0000u);
        uint32_t l01 = pack_bf16x2(v.y - hy, v.x - hx);
        uint32_t l23 = pack_bf16x2(v.w - hw, v.z - hz);
        int eo = r * KST + c4 * 4;
        *(uint2*)(Ahi + eo) = make_uint2(h01, h23);
        *(uint2*)(Alo + eo) = make_uint2(l01, l23);
    }
    asm volatile("cp.async.wait_group 0;" ::: "memory");
    __syncthreads();

    // ---- MMA: warp w covers rows m0..m0+31, cols n0..n0+47; ks-outer fused terms ----
    const int w  = tid >> 5;
    const int l  = tid & 31;
    const int m0 = (w & 3) * 32;
    const int n0 = (w >> 2) * 48;

    uint32_t aoff[2], boff[3];
#pragma unroll
    for (int mt = 0; mt < 2; mt++)
        aoff[mt] = (uint32_t)((m0 + mt * 16 + (l & 15)) * KST + (l >> 4) * 8);
#pragma unroll
    for (int p = 0; p < 3; p++)
        boff[p] = (uint32_t)((n0 + p * 16 + (l >> 4) * 8 + (l & 7)) * KST + ((l >> 3) & 1) * 8);

    float acc[2][6][4];
#pragma unroll
    for (int mt = 0; mt < 2; mt++)
#pragma unroll
        for (int nt = 0; nt < 6; nt++)
#pragma unroll
            for (int q = 0; q < 4; q++) acc[mt][nt][q] = 0.f;

#pragma unroll
    for (int ks = 0; ks < 6; ks++) {
        const uint32_t k0 = ks * 16;
        uint32_t aH[2][4], aL[2][4], bH[6][2], bL[6][2];
#pragma unroll
        for (int mt = 0; mt < 2; mt++) {
            ldsm4(aH[mt][0], aH[mt][1], aH[mt][2], aH[mt][3],
                  sbase + SM_AHI + 2 * (aoff[mt] + k0));
            ldsm4(aL[mt][0], aL[mt][1], aL[mt][2], aL[mt][3],
                  sbase + SM_ALO + 2 * (aoff[mt] + k0));
        }
#pragma unroll
        for (int p = 0; p < 3; p++) {
            ldsm4(bH[2 * p][0], bH[2 * p][1], bH[2 * p + 1][0], bH[2 * p + 1][1],
                  sbase + SM_BHI + 2 * (boff[p] + k0));
            ldsm4(bL[2 * p][0], bL[2 * p][1], bL[2 * p + 1][0], bL[2 * p + 1][1],
                  sbase + SM_BLO + 2 * (boff[p] + k0));
        }
#pragma unroll
        for (int mt = 0; mt < 2; mt++)
#pragma unroll
            for (int nt = 0; nt < 6; nt++)
                MMA_BF16(acc[mt][nt], aH[mt][0], aH[mt][1], aH[mt][2], aH[mt][3],
                         bH[nt][0], bH[nt][1]);
#pragma unroll
        for (int mt = 0; mt < 2; mt++)
#pragma unroll
            for (int nt = 0; nt < 6; nt++)
                MMA_BF16(acc[mt][nt], aH[mt][0], aH[mt][1], aH[mt][2], aH[mt][3],
                         bL[nt][0], bL[nt][1]);
#pragma unroll
        for (int mt = 0; mt < 2; mt++)
#pragma unroll
            for (int nt = 0; nt < 6; nt++)
                MMA_BF16(acc[mt][nt], aL[mt][0], aL[mt][1], aL[mt][2], aL[mt][3],
                         bH[nt][0], bH[nt][1]);
    }

    // ---- epilogue straight from registers ----
    const int lr = l >> 2;
    const int lk = 2 * (l & 3);
#pragma unroll
    for (int mt = 0; mt < 2; mt++) {
#pragma unroll
        for (int nt = 0; nt < 6; nt++) {
            int col = n0 + nt * 8 + lk;
            float bx = Bsm[col], by = Bsm[col + 1];
            int r1 = row0 + m0 + mt * 16 + lr;
            int r2 = r1 + 8;
            if (r1 < N_NODES) {
                float gx = gelu_exact(acc[mt][nt][0] + bx);
                float gy = gelu_exact(acc[mt][nt][1] + by);
                size_t o = (size_t)r1 * HID + col;
                if (MODE == 2) {
                    float2 xv = *(const float2*)(g_aggr + o);
                    gx += xv.x; gy += xv.y;
                }
                *(float2*)(out + o) = make_float2(gx, gy);
            }
            if (r2 < N_NODES) {
                float gx = gelu_exact(acc[mt][nt][2] + bx);
                float gy = gelu_exact(acc[mt][nt][3] + by);
                size_t o = (size_t)r2 * HID + col;
                if (MODE == 2) {
                    float2 xv = *(const float2*)(g_aggr + o);
                    gx += xv.x; gy += xv.y;
                }
                *(float2*)(out + o) = make_float2(gx, gy);
            }
        }
    }
}

// Edge scatter: aggr[dst] += h[src] * bases, one float4 per thread (fully coalesced).
__global__ __launch_bounds__(256)
void edge_kernel(const float* __restrict__ bases,
                 const int* __restrict__ src,
                 const int* __restrict__ dst) {
    int idx = blockIdx.x * 256 + threadIdx.x;
    if (idx >= N_EDGES * 24) return;
    int e = idx / 24;
    int c = idx - e * 24;
    int s = src[e];
    int d = dst[e];
    float4 b  = ((const float4*)bases)[idx];
    float4 hv = ((const float4*)(g_h + (size_t)s * HID))[c];
    float4 m  = make_float4(b.x * hv.x, b.y * hv.y, b.z * hv.z, b.w * hv.w);
    float* p = g_aggr + (size_t)d * HID + c * 4;
    asm volatile("red.global.add.v4.f32 [%0], {%1, %2, %3, %4};"
                 :: "l"(p), "f"(m.x), "f"(m.y), "f"(m.z), "f"(m.w)
                 : "memory");
}

extern "C" void kernel_launch(void* const* d_in, const int* in_sizes, int n_in,
                              void* d_out, int out_size) {
    const float* x_feat = (const float*)d_in[0];
    const float* bases  = (const float*)d_in[1];
    const float* W_pre  = (const float*)d_in[2];
    const float* b_pre  = (const float*)d_in[3];
    const float* W1     = (const float*)d_in[4];
    const float* b1     = (const float*)d_in[5];
    const float* W2     = (const float*)d_in[6];
    const float* b2     = (const float*)d_in[7];
    const int*   src    = (const int*)d_in[8];
    const int*   dst    = (const int*)d_in[9];
    float* out = (float*)d_out;

    cudaFuncSetAttribute(gemm_kernel<0>, cudaFuncAttributeMaxDynamicSharedMemorySize, SM_TOT);
    cudaFuncSetAttribute(gemm_kernel<1>, cudaFuncAttributeMaxDynamicSharedMemorySize, SM_TOT);
    cudaFuncSetAttribute(gemm_kernel<2>, cudaFuncAttributeMaxDynamicSharedMemorySize, SM_TOT);

    float* g_h_p;    cudaGetSymbolAddress((void**)&g_h_p, g_h);
    float* g_t_p;    cudaGetSymbolAddress((void**)&g_t_p, g_t);
    float* g_aggr_p; cudaGetSymbolAddress((void**)&g_aggr_p, g_aggr);
    unsigned char* wcvt_p; cudaGetSymbolAddress((void**)&wcvt_p, g_wcvt);

    const int gemm_grid = (N_NODES + BM - 1) / BM;   // 391
    const int edge_grid = (N_EDGES * 24 + 255) / 256;

    wconv_kernel<<<96, 256>>>(W_pre, W1, W2);
    // 1) h = gelu(x_feat @ W_pre + b_pre); g_aggr = x_feat
    gemm_kernel<0><<<gemm_grid, 256, SM_TOT>>>(x_feat, wcvt_p, b_pre, g_h_p);
    // 2) g_aggr[dst] += h[src] * bases   (g_aggr becomes x = x_feat + aggr)
    edge_kernel<<<edge_grid, 256>>>(bases, src, dst);
    // 3) t = gelu(x @ W1 + b1)
    gemm_kernel<1><<<gemm_grid, 256, SM_TOT>>>(g_aggr_p, wcvt_p + WMAT_BYTES, b1, g_t_p);
    // 4) out = x + gelu(t @ W2 + b2)
    gemm_kernel<2><<<gemm_grid, 256, SM_TOT>>>(g_t_p, wcvt_p + 2 * WMAT_BYTES, b2, out);
}